// round 16
// baseline (speedup 1.0000x reference)
#include <cuda_runtime.h>
#include <stdint.h>
#include <math.h>
#include <mma.h>

using namespace nvcuda;

#define M_TOK   4096     // B*L
#define D_MODEL 256
#define HDIM    512      // H*DH
#define L_SEQ   512
#define NHEAD   8
#define DHEAD   64
#define DEPTH_N 16
#define INNER_N 1024

// ---------------- scratch (device globals; no allocation allowed) -------------
__device__ float g_x   [M_TOK * D_MODEL];
__device__ float g_h   [M_TOK * D_MODEL];
__device__ float g_t   [M_TOK * D_MODEL];
__device__ float g_q   [M_TOK * HDIM];
__device__ float g_k   [M_TOK * HDIM];
__device__ float g_v   [M_TOK * HDIM];
__device__ float g_attn[M_TOK * HDIM];
__device__ float g_ua  [M_TOK * INNER_N];

// ---------------- cp.async helpers -------------------------------------------
__device__ __forceinline__ void cp16(uint32_t dst, const float* src) {
    asm volatile("cp.async.ca.shared.global [%0], [%1], 16;\n" :: "r"(dst), "l"(src));
}
__device__ __forceinline__ void cp_commit() {
    asm volatile("cp.async.commit_group;\n");
}
__device__ __forceinline__ void cp_wait1() {
    asm volatile("cp.async.wait_group 1;\n");
}
__device__ __forceinline__ void cp_wait0() {
    asm volatile("cp.async.wait_group 0;\n");
}

// ---------------- fast exp on FMA/ALU pipes -----------------------------------
__device__ __forceinline__ float fexp(float x) {
    float y = fmaxf(x, -87.0f) * 1.442695041f;
    float n = rintf(y);
    float f = y - n;
    float p = 0.0013333558f;
    p = fmaf(p, f, 0.0096181291f);
    p = fmaf(p, f, 0.0555041087f);
    p = fmaf(p, f, 0.2402265070f);
    p = fmaf(p, f, 0.6931471806f);
    p = fmaf(p, f, 1.0f);
    int e = ((int)n + 127) << 23;
    return __int_as_float(e) * p;
}

// ---------------- LayerNorm helper (blockDim.x == 256 == D_MODEL) ------------
__device__ __forceinline__ void ln_write(float v, const float* __restrict__ g,
                                         const float* __restrict__ b,
                                         float* __restrict__ y, int row) {
    int d = threadIdx.x;
    float s = v, s2 = v * v;
    #pragma unroll
    for (int o = 16; o > 0; o >>= 1) {
        s  += __shfl_down_sync(0xffffffffu, s,  o);
        s2 += __shfl_down_sync(0xffffffffu, s2, o);
    }
    __shared__ float ws[8], ws2[8];
    __shared__ float mean_s, inv_s;
    int w = threadIdx.x >> 5, lane = threadIdx.x & 31;
    if (lane == 0) { ws[w] = s; ws2[w] = s2; }
    __syncthreads();
    if (threadIdx.x == 0) {
        float t = 0.f, t2 = 0.f;
        #pragma unroll
        for (int i = 0; i < 8; i++) { t += ws[i]; t2 += ws2[i]; }
        float mu  = t  * (1.f / 256.f);
        float var = t2 * (1.f / 256.f) - mu * mu;
        mean_s = mu;
        inv_s  = rsqrtf(var + 1e-5f);
    }
    __syncthreads();
    y[(size_t)row * D_MODEL + d] = (v - mean_s) * inv_s * g[d] + b[d];
}

__global__ void embed_ln_kernel(const int* __restrict__ seq,
                                const float* __restrict__ emb,
                                const float* __restrict__ g,
                                const float* __restrict__ b,
                                float* __restrict__ y) {
    int row = blockIdx.x;
    float v = emb[(size_t)seq[row] * D_MODEL + threadIdx.x];
    ln_write(v, g, b, y, row);
}

__global__ void ln_kernel(const float* __restrict__ x,
                          const float* __restrict__ g,
                          const float* __restrict__ b,
                          float* __restrict__ y) {
    int row = blockIdx.x;
    float v = x[(size_t)row * D_MODEL + threadIdx.x];
    ln_write(v, g, b, y, row);
}

// x[row] += t[row] (+bias); then y[row] = LN(x[row])
__global__ void add_ln_kernel(float* __restrict__ x,
                              const float* __restrict__ t,
                              const float* __restrict__ bias,
                              const float* __restrict__ g,
                              const float* __restrict__ b,
                              float* __restrict__ y) {
    int row = blockIdx.x;
    int d = threadIdx.x;
    size_t idx = (size_t)row * D_MODEL + d;
    float v = x[idx] + t[idx];
    if (bias) v += bias[d];
    x[idx] = v;
    ln_write(v, g, b, y, row);
}

// ---------------- tf32 WMMA GEMM body: 128x64 tile, BK=32, double-buffered ---
#define AS_STAGE (128 * 36)
#define BS_STAGE (32 * 68)
#define GEMM_SMEM ((2 * AS_STAGE + 2 * BS_STAGE) * 4)

__device__ __forceinline__ void gemm_body(const float* __restrict__ A,
                                          const float* __restrict__ W,
                                          float* __restrict__ C,
                                          int N, int K, int bm, int bn) {
    extern __shared__ float dyn[];
    float* As = dyn;
    float* Bs = dyn + 2 * AS_STAGE;
    const int tid = threadIdx.x;
    const int warp = tid >> 5, wm = warp & 3, wn = warp >> 2;
    const int arow = tid >> 1, acol = (tid & 1) * 16;
    const int brow = tid >> 3, bcol = (tid & 7) * 8;
    uint32_t as_u = (uint32_t)__cvta_generic_to_shared(As);
    uint32_t bs_u = (uint32_t)__cvta_generic_to_shared(Bs);

    wmma::fragment<wmma::accumulator, 16, 16, 8, float> acc[2][2];
    #pragma unroll
    for (int i = 0; i < 2; i++)
        #pragma unroll
        for (int j = 0; j < 2; j++)
            wmma::fill_fragment(acc[i][j], 0.0f);

    const int nk = K >> 5;

    {
        const float* ap = A + (size_t)(bm + arow) * K + acol;
        uint32_t ad = as_u + (uint32_t)((arow * 36 + acol) * 4);
        #pragma unroll
        for (int i = 0; i < 4; i++) cp16(ad + i * 16, ap + i * 4);
        const float* bp = W + (size_t)brow * N + bn + bcol;
        uint32_t bd = bs_u + (uint32_t)((brow * 68 + bcol) * 4);
        cp16(bd, bp); cp16(bd + 16, bp + 4);
        cp_commit();
    }

    for (int kt = 0; kt < nk; kt++) {
        int st = kt & 1;
        if (kt + 1 < nk) {
            int k0 = (kt + 1) << 5;
            int s2 = st ^ 1;
            const float* ap = A + (size_t)(bm + arow) * K + k0 + acol;
            uint32_t ad = as_u + (uint32_t)((s2 * AS_STAGE + arow * 36 + acol) * 4);
            #pragma unroll
            for (int i = 0; i < 4; i++) cp16(ad + i * 16, ap + i * 4);
            const float* bp = W + (size_t)(k0 + brow) * N + bn + bcol;
            uint32_t bd = bs_u + (uint32_t)((s2 * BS_STAGE + brow * 68 + bcol) * 4);
            cp16(bd, bp); cp16(bd + 16, bp + 4);
            cp_commit();
            cp_wait1();
        } else {
            cp_wait0();
        }
        __syncthreads();

        const float* Ab = As + st * AS_STAGE;
        const float* Bb = Bs + st * BS_STAGE;
        #pragma unroll
        for (int kk = 0; kk < 4; kk++) {
            wmma::fragment<wmma::matrix_a, 16, 16, 8, wmma::precision::tf32, wmma::row_major> af[2];
            wmma::fragment<wmma::matrix_b, 16, 16, 8, wmma::precision::tf32, wmma::row_major> bf[2];
            #pragma unroll
            for (int i = 0; i < 2; i++) {
                wmma::load_matrix_sync(af[i], Ab + (wm * 32 + i * 16) * 36 + kk * 8, 36);
                #pragma unroll
                for (int e = 0; e < af[i].num_elements; e++)
                    af[i].x[e] = wmma::__float_to_tf32(af[i].x[e]);
            }
            #pragma unroll
            for (int j = 0; j < 2; j++) {
                wmma::load_matrix_sync(bf[j], Bb + (kk * 8) * 68 + wn * 32 + j * 16, 68);
                #pragma unroll
                for (int e = 0; e < bf[j].num_elements; e++)
                    bf[j].x[e] = wmma::__float_to_tf32(bf[j].x[e]);
            }
            #pragma unroll
            for (int i = 0; i < 2; i++)
                #pragma unroll
                for (int j = 0; j < 2; j++)
                    wmma::mma_sync(acc[i][j], af[i], bf[j], acc[i][j]);
        }
        __syncthreads();
    }

    #pragma unroll
    for (int i = 0; i < 2; i++)
        #pragma unroll
        for (int j = 0; j < 2; j++)
            wmma::store_matrix_sync(C + (size_t)(bm + wm * 32 + i * 16) * N + bn + wn * 32 + j * 16,
                                    acc[i][j], N, wmma::mem_row_major);
}

// fused QKV: blockIdx.x in [0,24); sel = x>>3 chooses weight/output
__global__ __launch_bounds__(256) void gemm_qkv(const float* __restrict__ A,
                                                const float* __restrict__ wq,
                                                const float* __restrict__ wk,
                                                const float* __restrict__ wv,
                                                float* __restrict__ qb,
                                                float* __restrict__ kb,
                                                float* __restrict__ vb) {
    int sel = blockIdx.x >> 3;
    const float* W = (sel == 0) ? wq : (sel == 1) ? wk : wv;
    float* C = (sel == 0) ? qb : (sel == 1) ? kb : vb;
    gemm_body(A, W, C, HDIM, D_MODEL, blockIdx.y << 7, (blockIdx.x & 7) << 6);
}

// ---------------- 64x64-tile GEMM for small-N (Wo, W2): full chip fill --------
// 8 warps, warp tile 32x16 (wm in {0,1}, wn in 0..3), BK=32, double-buffered.
#define AS64_STAGE (64 * 36)
#define GEMM64_SMEM ((2 * AS64_STAGE + 2 * BS_STAGE) * 4)

__global__ __launch_bounds__(256) void gemm64_tf32(const float* __restrict__ A,
                                                   const float* __restrict__ W,
                                                   float* __restrict__ C, int N, int K) {
    extern __shared__ float dyn[];
    float* As = dyn;
    float* Bs = dyn + 2 * AS64_STAGE;
    const int tid = threadIdx.x;
    const int warp = tid >> 5, wm = warp & 1, wn = warp >> 1;
    const int bm = blockIdx.y << 6, bn = blockIdx.x << 6;
    const int arow = tid >> 2, acol = (tid & 3) * 8;   // 64 rows x 32 cols
    const int brow = tid >> 3, bcol = (tid & 7) * 8;   // 32 rows x 64 cols
    uint32_t as_u = (uint32_t)__cvta_generic_to_shared(As);
    uint32_t bs_u = (uint32_t)__cvta_generic_to_shared(Bs);

    wmma::fragment<wmma::accumulator, 16, 16, 8, float> acc[2];
    wmma::fill_fragment(acc[0], 0.0f);
    wmma::fill_fragment(acc[1], 0.0f);

    const int nk = K >> 5;

    {
        const float* ap = A + (size_t)(bm + arow) * K + acol;
        uint32_t ad = as_u + (uint32_t)((arow * 36 + acol) * 4);
        cp16(ad, ap); cp16(ad + 16, ap + 4);
        const float* bp = W + (size_t)brow * N + bn + bcol;
        uint32_t bd = bs_u + (uint32_t)((brow * 68 + bcol) * 4);
        cp16(bd, bp); cp16(bd + 16, bp + 4);
        cp_commit();
    }

    for (int kt = 0; kt < nk; kt++) {
        int st = kt & 1;
        if (kt + 1 < nk) {
            int k0 = (kt + 1) << 5;
            int s2 = st ^ 1;
            const float* ap = A + (size_t)(bm + arow) * K + k0 + acol;
            uint32_t ad = as_u + (uint32_t)((s2 * AS64_STAGE + arow * 36 + acol) * 4);
            cp16(ad, ap); cp16(ad + 16, ap + 4);
            const float* bp = W + (size_t)(k0 + brow) * N + bn + bcol;
            uint32_t bd = bs_u + (uint32_t)((s2 * BS_STAGE + brow * 68 + bcol) * 4);
            cp16(bd, bp); cp16(bd + 16, bp + 4);
            cp_commit();
            cp_wait1();
        } else {
            cp_wait0();
        }
        __syncthreads();

        const float* Ab = As + st * AS64_STAGE;
        const float* Bb = Bs + st * BS_STAGE;
        #pragma unroll
        for (int kk = 0; kk < 4; kk++) {
            wmma::fragment<wmma::matrix_a, 16, 16, 8, wmma::precision::tf32, wmma::row_major> af[2];
            wmma::fragment<wmma::matrix_b, 16, 16, 8, wmma::precision::tf32, wmma::row_major> bf;
            #pragma unroll
            for (int i = 0; i < 2; i++) {
                wmma::load_matrix_sync(af[i], Ab + (wm * 32 + i * 16) * 36 + kk * 8, 36);
                #pragma unroll
                for (int e = 0; e < af[i].num_elements; e++)
                    af[i].x[e] = wmma::__float_to_tf32(af[i].x[e]);
            }
            wmma::load_matrix_sync(bf, Bb + (kk * 8) * 68 + wn * 16, 68);
            #pragma unroll
            for (int e = 0; e < bf.num_elements; e++)
                bf.x[e] = wmma::__float_to_tf32(bf.x[e]);
            #pragma unroll
            for (int i = 0; i < 2; i++)
                wmma::mma_sync(acc[i], af[i], bf, acc[i]);
        }
        __syncthreads();
    }

    #pragma unroll
    for (int i = 0; i < 2; i++)
        wmma::store_matrix_sync(C + (size_t)(bm + wm * 32 + i * 16) * N + bn + wn * 16,
                                acc[i], N, wmma::mem_row_major);
}

// ---------------- fused W1 GEMM + GEGLU: ua = (hW1v+b1v)*gelu(hW1g+b1g) ------
#define W1_SMEM ((2 * AS_STAGE + 4 * BS_STAGE) * 4)

__global__ __launch_bounds__(256, 2) void gemm_w1glu(const float* __restrict__ A,
                                                     const float* __restrict__ W1,
                                                     const float* __restrict__ b1,
                                                     float* __restrict__ out) {
    extern __shared__ float dyn[];
    float* As = dyn;
    float* Bv = dyn + 2 * AS_STAGE;
    float* Bg = dyn + 2 * AS_STAGE + 2 * BS_STAGE;
    const int tid = threadIdx.x;
    const int warp = tid >> 5, wm = warp & 3, wn = warp >> 2;
    const int bm = blockIdx.y << 7, bn = blockIdx.x << 6;
    const int arow = tid >> 1, acol = (tid & 1) * 16;
    const int brow = tid >> 3, bcol = (tid & 7) * 8;
    uint32_t as_u = (uint32_t)__cvta_generic_to_shared(As);
    uint32_t bv_u = (uint32_t)__cvta_generic_to_shared(Bv);
    uint32_t bg_u = (uint32_t)__cvta_generic_to_shared(Bg);

    wmma::fragment<wmma::accumulator, 16, 16, 8, float> accv[2][2], accg[2][2];
    #pragma unroll
    for (int i = 0; i < 2; i++)
        #pragma unroll
        for (int j = 0; j < 2; j++) {
            wmma::fill_fragment(accv[i][j], 0.0f);
            wmma::fill_fragment(accg[i][j], 0.0f);
        }

    const int NW = 2 * INNER_N;
    {
        const float* ap = A + (size_t)(bm + arow) * D_MODEL + acol;
        uint32_t ad = as_u + (uint32_t)((arow * 36 + acol) * 4);
        #pragma unroll
        for (int i = 0; i < 4; i++) cp16(ad + i * 16, ap + i * 4);
        const float* bpv = W1 + (size_t)brow * NW + bn + bcol;
        uint32_t bdv = bv_u + (uint32_t)((brow * 68 + bcol) * 4);
        cp16(bdv, bpv); cp16(bdv + 16, bpv + 4);
        const float* bpg = bpv + INNER_N;
        uint32_t bdg = bg_u + (uint32_t)((brow * 68 + bcol) * 4);
        cp16(bdg, bpg); cp16(bdg + 16, bpg + 4);
        cp_commit();
    }

    const int nk = D_MODEL >> 5;
    for (int kt = 0; kt < nk; kt++) {
        int st = kt & 1;
        if (kt + 1 < nk) {
            int k0 = (kt + 1) << 5;
            int s2 = st ^ 1;
            const float* ap = A + (size_t)(bm + arow) * D_MODEL + k0 + acol;
            uint32_t ad = as_u + (uint32_t)((s2 * AS_STAGE + arow * 36 + acol) * 4);
            #pragma unroll
            for (int i = 0; i < 4; i++) cp16(ad + i * 16, ap + i * 4);
            const float* bpv = W1 + (size_t)(k0 + brow) * NW + bn + bcol;
            uint32_t bdv = bv_u + (uint32_t)((s2 * BS_STAGE + brow * 68 + bcol) * 4);
            cp16(bdv, bpv); cp16(bdv + 16, bpv + 4);
            const float* bpg = bpv + INNER_N;
            uint32_t bdg = bg_u + (uint32_t)((s2 * BS_STAGE + brow * 68 + bcol) * 4);
            cp16(bdg, bpg); cp16(bdg + 16, bpg + 4);
            cp_commit();
            cp_wait1();
        } else {
            cp_wait0();
        }
        __syncthreads();

        const float* Ab  = As + st * AS_STAGE;
        const float* Bvb = Bv + st * BS_STAGE;
        const float* Bgb = Bg + st * BS_STAGE;
        #pragma unroll
        for (int kk = 0; kk < 4; kk++) {
            wmma::fragment<wmma::matrix_a, 16, 16, 8, wmma::precision::tf32, wmma::row_major> af[2];
            #pragma unroll
            for (int i = 0; i < 2; i++) {
                wmma::load_matrix_sync(af[i], Ab + (wm * 32 + i * 16) * 36 + kk * 8, 36);
                #pragma unroll
                for (int e = 0; e < af[i].num_elements; e++)
                    af[i].x[e] = wmma::__float_to_tf32(af[i].x[e]);
            }
            #pragma unroll
            for (int j = 0; j < 2; j++) {
                wmma::fragment<wmma::matrix_b, 16, 16, 8, wmma::precision::tf32, wmma::row_major> bfv, bfg;
                wmma::load_matrix_sync(bfv, Bvb + (kk * 8) * 68 + wn * 32 + j * 16, 68);
                wmma::load_matrix_sync(bfg, Bgb + (kk * 8) * 68 + wn * 32 + j * 16, 68);
                #pragma unroll
                for (int e = 0; e < bfv.num_elements; e++) {
                    bfv.x[e] = wmma::__float_to_tf32(bfv.x[e]);
                    bfg.x[e] = wmma::__float_to_tf32(bfg.x[e]);
                }
                #pragma unroll
                for (int i = 0; i < 2; i++) {
                    wmma::mma_sync(accv[i][j], af[i], bfv, accv[i][j]);
                    wmma::mma_sync(accg[i][j], af[i], bfg, accg[i][j]);
                }
            }
        }
        __syncthreads();
    }

    float* Sv = dyn;
    float* Sg = dyn + 2 * AS_STAGE;
    #pragma unroll
    for (int i = 0; i < 2; i++)
        #pragma unroll
        for (int j = 0; j < 2; j++) {
            wmma::store_matrix_sync(&Sv[(wm * 32 + i * 16) * 68 + wn * 32 + j * 16],
                                    accv[i][j], 68, wmma::mem_row_major);
            wmma::store_matrix_sync(&Sg[(wm * 32 + i * 16) * 68 + wn * 32 + j * 16],
                                    accg[i][j], 68, wmma::mem_row_major);
        }
    __syncthreads();

    const int er = tid >> 1, ec = (tid & 1) * 32;
    float* orow = out + (size_t)(bm + er) * INNER_N + bn;
    #pragma unroll
    for (int c = 0; c < 32; c++) {
        float vl = Sv[er * 68 + ec + c] + b1[bn + ec + c];
        float gt = Sg[er * 68 + ec + c] + b1[INNER_N + bn + ec + c];
        orow[ec + c] = vl * gt * normcdff(gt);
    }
}

// ---------------- single-pass attention (R11 version — best measured) --------
#define TS 68
#define OFF_K (128 * TS)
#define OFF_V (128 * TS + 64 * TS)
#define OFF_S (128 * TS + 2 * 64 * TS)
#define OFF_P (2 * 128 * TS + 2 * 64 * TS)
#define ATTN_SMEM ((OFF_P + 512) * 4)

__global__ __launch_bounds__(256, 2) void attn_kernel(const float* __restrict__ q,
                                                      const float* __restrict__ k,
                                                      const float* __restrict__ v,
                                                      const int* __restrict__ mask,
                                                      float* __restrict__ o) {
    extern __shared__ float sm[];
    float* Qs = sm;                 // [128][TS]
    float* Ks = sm + OFF_K;         // [64][TS]
    float* Vs = sm + OFF_V;         // [64][TS]
    float* Ss = sm + OFF_S;         // [128][TS]
    float* penal = sm + OFF_P;      // [512]
    uint32_t smem_u = (uint32_t)__cvta_generic_to_shared(sm);

    const int tid = threadIdx.x;
    const int warp = tid >> 5;
    const int wm = warp & 3;
    const int wn = warp >> 2;
    const int qt = blockIdx.x;
    const int b  = blockIdx.y >> 3;
    const int h  = blockIdx.y & 7;
    const float slope = exp2f(-(float)(h + 1));
    const float scale = 0.125f;

    for (int j = tid; j < L_SEQ; j += 256)
        penal[j] = mask[b * L_SEQ + j] ? 0.f : -1e9f;

    {
        int lr = tid >> 1, lc = (tid & 1) * 32;
        const float* qp = q + (size_t)(b * L_SEQ + qt * 128 + lr) * HDIM + h * DHEAD + lc;
        #pragma unroll
        for (int i = 0; i < 8; i++)
            *(float4*)&Qs[lr * TS + lc + i * 4] = *(const float4*)(qp + i * 4);
    }

    const int kr = tid >> 2, kc = (tid & 3) * 16;
    const size_t kvbase = (size_t)(b * L_SEQ + kr) * HDIM + h * DHEAD + kc;
    const uint32_t kd = smem_u + (uint32_t)((OFF_K + kr * TS + kc) * 4);
    const uint32_t vd = smem_u + (uint32_t)((OFF_V + kr * TS + kc) * 4);

    {
        const float* kp = k + kvbase;
        #pragma unroll
        for (int i = 0; i < 4; i++) cp16(kd + i * 16, kp + i * 4);
        cp_commit();
    }
    __syncthreads();

    const int r = tid >> 1, p = tid & 1;
    const int ig = qt * 128 + r;

    float msh = -3e38f;
    for (int jj = 0; jj < 256; jj++) {
        int jg = p * 256 + jj;
        msh = fmaxf(msh, penal[jg] - slope * fabsf((float)(ig - jg)));
    }
    msh = fmaxf(msh, __shfl_xor_sync(0xffffffffu, msh, 1));

    float ssum = 0.f;
    wmma::fragment<wmma::accumulator, 16, 16, 8, float> oacc[2][2];
    #pragma unroll
    for (int i = 0; i < 2; i++)
        #pragma unroll
        for (int j = 0; j < 2; j++)
            wmma::fill_fragment(oacc[i][j], 0.f);

    for (int kt = 0; kt < 8; kt++) {
        {
            const float* vp = v + kvbase + (size_t)kt * 64 * HDIM;
            #pragma unroll
            for (int i = 0; i < 4; i++) cp16(vd + i * 16, vp + i * 4);
            cp_commit();
        }
        cp_wait1();
        __syncthreads();

        #pragma unroll
        for (int i = 0; i < 2; i++) {
            wmma::fragment<wmma::accumulator, 16, 16, 8, float> sacc[2];
            wmma::fill_fragment(sacc[0], 0.f);
            wmma::fill_fragment(sacc[1], 0.f);
            #pragma unroll
            for (int kk = 0; kk < 8; kk++) {
                wmma::fragment<wmma::matrix_a, 16, 16, 8, wmma::precision::tf32, wmma::row_major> af;
                wmma::load_matrix_sync(af, &Qs[(wm * 32 + i * 16) * TS + kk * 8], TS);
                #pragma unroll
                for (int j = 0; j < 2; j++) {
                    wmma::fragment<wmma::matrix_b, 16, 16, 8, wmma::precision::tf32, wmma::col_major> bf;
                    wmma::load_matrix_sync(bf, &Ks[(wn * 32 + j * 16) * TS + kk * 8], TS);
                    wmma::mma_sync(sacc[j], af, bf, sacc[j]);
                }
            }
            #pragma unroll
            for (int j = 0; j < 2; j++)
                wmma::store_matrix_sync(&Ss[(wm * 32 + i * 16) * TS + wn * 32 + j * 16],
                                        sacc[j], TS, wmma::mem_row_major);
        }
        __syncthreads();

        if (kt < 7) {
            const float* kp = k + kvbase + (size_t)(kt + 1) * 64 * HDIM;
            #pragma unroll
            for (int i = 0; i < 4; i++) cp16(kd + i * 16, kp + i * 4);
            cp_commit();
        }

        {
            float* Srow = Ss + r * TS;
            #pragma unroll
            for (int jj = 0; jj < 32; jj++) {
                int jl = p * 32 + jj, jg = kt * 64 + jl;
                float pre = penal[jg] - slope * fabsf((float)(ig - jg)) - msh;
                float e = fexp(fmaf(Srow[jl], scale, pre));
                Srow[jl] = e;
                ssum += e;
            }
        }
        if (kt < 7) cp_wait1(); else cp_wait0();
        __syncthreads();

        #pragma unroll
        for (int i = 0; i < 2; i++)
            #pragma unroll
            for (int kk = 0; kk < 8; kk++) {
                wmma::fragment<wmma::matrix_a, 16, 16, 8, wmma::precision::tf32, wmma::row_major> af;
                wmma::load_matrix_sync(af, &Ss[(wm * 32 + i * 16) * TS + kk * 8], TS);
                #pragma unroll
                for (int j = 0; j < 2; j++) {
                    wmma::fragment<wmma::matrix_b, 16, 16, 8, wmma::precision::tf32, wmma::row_major> bf;
                    wmma::load_matrix_sync(bf, &Vs[(kk * 8) * TS + wn * 32 + j * 16], TS);
                    wmma::mma_sync(oacc[i][j], af, bf, oacc[i][j]);
                }
            }
        __syncthreads();
    }

    ssum += __shfl_xor_sync(0xffffffffu, ssum, 1);
    const float inv = 1.f / ssum;

    #pragma unroll
    for (int i = 0; i < 2; i++)
        #pragma unroll
        for (int j = 0; j < 2; j++)
            wmma::store_matrix_sync(&Ss[(wm * 32 + i * 16) * TS + wn * 32 + j * 16],
                                    oacc[i][j], TS, wmma::mem_row_major);
    __syncthreads();

    {
        int ec = p * 32;
        float* op = o + (size_t)(b * L_SEQ + qt * 128 + r) * HDIM + h * DHEAD + ec;
        #pragma unroll
        for (int i = 0; i < 8; i++) {
            float4 vv = *(float4*)&Ss[r * TS + ec + i * 4];
            vv.x *= inv; vv.y *= inv; vv.z *= inv; vv.w *= inv;
            *(float4*)(op + i * 4) = vv;
        }
    }
}

// ---------------- final projection to 2 logits -------------------------------
__global__ void out_kernel(const float* __restrict__ hh,
                           const float* __restrict__ Wout,
                           const float* __restrict__ bout,
                           float* __restrict__ out) {
    int row = blockIdx.x;
    int d = threadIdx.x;
    float v = hh[(size_t)row * D_MODEL + d];
    float s0 = v * Wout[d * 2 + 0];
    float s1 = v * Wout[d * 2 + 1];
    #pragma unroll
    for (int o2 = 16; o2 > 0; o2 >>= 1) {
        s0 += __shfl_down_sync(0xffffffffu, s0, o2);
        s1 += __shfl_down_sync(0xffffffffu, s1, o2);
    }
    __shared__ float w0[8], w1[8];
    int w = threadIdx.x >> 5, lane = threadIdx.x & 31;
    if (lane == 0) { w0[w] = s0; w1[w] = s1; }
    __syncthreads();
    if (threadIdx.x == 0) {
        float t0 = 0.f, t1 = 0.f;
        #pragma unroll
        for (int i = 0; i < 8; i++) { t0 += w0[i]; t1 += w1[i]; }
        out[row * 2 + 0] = t0 + bout[0];
        out[row * 2 + 1] = t1 + bout[1];
    }
}

// ---------------- host orchestration -----------------------------------------
extern "C" void kernel_launch(void* const* d_in, const int* in_sizes, int n_in,
                              void* d_out, int out_size) {
    (void)in_sizes; (void)n_in; (void)out_size;
    const int*   seq  = (const int*)d_in[0];
    const int*   mask = (const int*)d_in[1];
    const float* emb  = (const float*)d_in[2];
    const float* png  = (const float*)d_in[3];
    const float* pnb  = (const float*)d_in[4];
    const float* ln1g = (const float*)d_in[5];
    const float* ln1b = (const float*)d_in[6];
    const float* Wq   = (const float*)d_in[7];
    const float* Wk   = (const float*)d_in[8];
    const float* Wv   = (const float*)d_in[9];
    const float* Wo   = (const float*)d_in[10];
    const float* ln2g = (const float*)d_in[11];
    const float* ln2b = (const float*)d_in[12];
    const float* W1   = (const float*)d_in[13];
    const float* b1   = (const float*)d_in[14];
    const float* W2   = (const float*)d_in[15];
    const float* b2   = (const float*)d_in[16];
    const float* fng  = (const float*)d_in[17];
    const float* fnb  = (const float*)d_in[18];
    const float* Wout = (const float*)d_in[19];
    const float* bout = (const float*)d_in[20];

    float *x, *h, *t, *qb, *kb, *vb, *ab, *uab;
    cudaGetSymbolAddress((void**)&x,   g_x);
    cudaGetSymbolAddress((void**)&h,   g_h);
    cudaGetSymbolAddress((void**)&t,   g_t);
    cudaGetSymbolAddress((void**)&qb,  g_q);
    cudaGetSymbolAddress((void**)&kb,  g_k);
    cudaGetSymbolAddress((void**)&vb,  g_v);
    cudaGetSymbolAddress((void**)&ab,  g_attn);
    cudaGetSymbolAddress((void**)&uab, g_ua);

    cudaFuncSetAttribute(attn_kernel, cudaFuncAttributeMaxDynamicSharedMemorySize, ATTN_SMEM);
    cudaFuncSetAttribute(gemm_qkv,    cudaFuncAttributeMaxDynamicSharedMemorySize, GEMM_SMEM);
    cudaFuncSetAttribute(gemm64_tf32, cudaFuncAttributeMaxDynamicSharedMemorySize, GEMM64_SMEM);
    cudaFuncSetAttribute(gemm_w1glu,  cudaFuncAttributeMaxDynamicSharedMemorySize, W1_SMEM);

    embed_ln_kernel<<<M_TOK, 256>>>(seq, emb, png, pnb, x);
    ln_kernel<<<M_TOK, 256>>>(x, ln1g, ln1b, h);

    for (int l = 0; l < DEPTH_N; l++) {
        const float* wq  = Wq  + (size_t)l * D_MODEL * HDIM;
        const float* wk  = Wk  + (size_t)l * D_MODEL * HDIM;
        const float* wv  = Wv  + (size_t)l * D_MODEL * HDIM;
        const float* wo  = Wo  + (size_t)l * HDIM * D_MODEL;
        const float* w1  = W1  + (size_t)l * D_MODEL * 2 * INNER_N;
        const float* bb1 = b1  + (size_t)l * 2 * INNER_N;
        const float* w2  = W2  + (size_t)l * INNER_N * D_MODEL;
        const float* bb2 = b2  + (size_t)l * D_MODEL;

        gemm_qkv<<<dim3(24, 32), 256, GEMM_SMEM>>>(h, wq, wk, wv, qb, kb, vb);

        attn_kernel<<<dim3(L_SEQ / 128, 8 * NHEAD), 256, ATTN_SMEM>>>(qb, kb, vb, mask, ab);

        gemm64_tf32<<<dim3(D_MODEL / 64, M_TOK / 64), 256, GEMM64_SMEM>>>(ab, wo, t, D_MODEL, HDIM);
        add_ln_kernel<<<M_TOK, 256>>>(x, t, nullptr, ln2g + l * D_MODEL, ln2b + l * D_MODEL, h);

        gemm_w1glu<<<dim3(INNER_N / 64, 32), 256, W1_SMEM>>>(h, w1, bb1, uab);

        gemm64_tf32<<<dim3(D_MODEL / 64, M_TOK / 64), 256, GEMM64_SMEM>>>(uab, w2, t, D_MODEL, INNER_N);
        if (l < DEPTH_N - 1)
            add_ln_kernel<<<M_TOK, 256>>>(x, t, bb2, ln1g + (l + 1) * D_MODEL,
                                          ln1b + (l + 1) * D_MODEL, h);
        else
            add_ln_kernel<<<M_TOK, 256>>>(x, t, bb2, fng, fnb, h);
    }

    out_kernel<<<M_TOK, 256>>>(h, Wout, bout, (float*)d_out);
}

// round 17
// speedup vs baseline: 1.0275x; 1.0275x over previous
#include <cuda_runtime.h>
#include <stdint.h>
#include <math.h>
#include <mma.h>

using namespace nvcuda;

#define M_TOK   4096     // B*L
#define D_MODEL 256
#define HDIM    512      // H*DH
#define L_SEQ   512
#define NHEAD   8
#define DHEAD   64
#define DEPTH_N 16
#define INNER_N 1024

// ---------------- scratch (device globals; no allocation allowed) -------------
__device__ float g_x   [M_TOK * D_MODEL];
__device__ float g_h   [M_TOK * D_MODEL];
__device__ float g_t0  [M_TOK * D_MODEL];
__device__ float g_t1  [M_TOK * D_MODEL];
__device__ float g_q   [M_TOK * HDIM];
__device__ float g_k   [M_TOK * HDIM];
__device__ float g_v   [M_TOK * HDIM];
__device__ float g_attn[M_TOK * HDIM];
__device__ float g_ua  [M_TOK * INNER_N];

// ---------------- cp.async helpers -------------------------------------------
__device__ __forceinline__ void cp16(uint32_t dst, const float* src) {
    asm volatile("cp.async.ca.shared.global [%0], [%1], 16;\n" :: "r"(dst), "l"(src));
}
__device__ __forceinline__ void cp_commit() {
    asm volatile("cp.async.commit_group;\n");
}
__device__ __forceinline__ void cp_wait1() {
    asm volatile("cp.async.wait_group 1;\n");
}
__device__ __forceinline__ void cp_wait0() {
    asm volatile("cp.async.wait_group 0;\n");
}

// ---------------- fast exp on FMA/ALU pipes -----------------------------------
__device__ __forceinline__ float fexp(float x) {
    float y = fmaxf(x, -87.0f) * 1.442695041f;
    float n = rintf(y);
    float f = y - n;
    float p = 0.0013333558f;
    p = fmaf(p, f, 0.0096181291f);
    p = fmaf(p, f, 0.0555041087f);
    p = fmaf(p, f, 0.2402265070f);
    p = fmaf(p, f, 0.6931471806f);
    p = fmaf(p, f, 1.0f);
    int e = ((int)n + 127) << 23;
    return __int_as_float(e) * p;
}

// ---------------- LayerNorm helper (blockDim.x == 256 == D_MODEL) ------------
__device__ __forceinline__ void ln_write(float v, const float* __restrict__ g,
                                         const float* __restrict__ b,
                                         float* __restrict__ y, int row) {
    int d = threadIdx.x;
    float s = v, s2 = v * v;
    #pragma unroll
    for (int o = 16; o > 0; o >>= 1) {
        s  += __shfl_down_sync(0xffffffffu, s,  o);
        s2 += __shfl_down_sync(0xffffffffu, s2, o);
    }
    __shared__ float ws[8], ws2[8];
    __shared__ float mean_s, inv_s;
    int w = threadIdx.x >> 5, lane = threadIdx.x & 31;
    if (lane == 0) { ws[w] = s; ws2[w] = s2; }
    __syncthreads();
    if (threadIdx.x == 0) {
        float t = 0.f, t2 = 0.f;
        #pragma unroll
        for (int i = 0; i < 8; i++) { t += ws[i]; t2 += ws2[i]; }
        float mu  = t  * (1.f / 256.f);
        float var = t2 * (1.f / 256.f) - mu * mu;
        mean_s = mu;
        inv_s  = rsqrtf(var + 1e-5f);
    }
    __syncthreads();
    y[(size_t)row * D_MODEL + d] = (v - mean_s) * inv_s * g[d] + b[d];
}

__global__ void embed_ln_kernel(const int* __restrict__ seq,
                                const float* __restrict__ emb,
                                const float* __restrict__ g,
                                const float* __restrict__ b,
                                float* __restrict__ y) {
    int row = blockIdx.x;
    float v = emb[(size_t)seq[row] * D_MODEL + threadIdx.x];
    ln_write(v, g, b, y, row);
}

__global__ void ln_kernel(const float* __restrict__ x,
                          const float* __restrict__ g,
                          const float* __restrict__ b,
                          float* __restrict__ y) {
    int row = blockIdx.x;
    float v = x[(size_t)row * D_MODEL + threadIdx.x];
    ln_write(v, g, b, y, row);
}

// x[row] += t0[row] + t1[row] (+bias); then y[row] = LN(x[row])
__global__ void add_ln_kernel(float* __restrict__ x,
                              const float* __restrict__ t0,
                              const float* __restrict__ t1,
                              const float* __restrict__ bias,
                              const float* __restrict__ g,
                              const float* __restrict__ b,
                              float* __restrict__ y) {
    int row = blockIdx.x;
    int d = threadIdx.x;
    size_t idx = (size_t)row * D_MODEL + d;
    float v = x[idx] + t0[idx] + t1[idx];
    if (bias) v += bias[d];
    x[idx] = v;
    ln_write(v, g, b, y, row);
}

// ---------------- tf32 WMMA GEMM body: 128x64 tile, BK=32, double-buffered ---
// lda = row stride of A (original K); Kit = iteration count for this call.
#define AS_STAGE (128 * 36)
#define BS_STAGE (32 * 68)
#define GEMM_SMEM ((2 * AS_STAGE + 2 * BS_STAGE) * 4)

__device__ __forceinline__ void gemm_body(const float* __restrict__ A, int lda,
                                          const float* __restrict__ W,
                                          float* __restrict__ C,
                                          int N, int Kit, int bm, int bn) {
    extern __shared__ float dyn[];
    float* As = dyn;
    float* Bs = dyn + 2 * AS_STAGE;
    const int tid = threadIdx.x;
    const int warp = tid >> 5, wm = warp & 3, wn = warp >> 2;
    const int arow = tid >> 1, acol = (tid & 1) * 16;
    const int brow = tid >> 3, bcol = (tid & 7) * 8;
    uint32_t as_u = (uint32_t)__cvta_generic_to_shared(As);
    uint32_t bs_u = (uint32_t)__cvta_generic_to_shared(Bs);

    wmma::fragment<wmma::accumulator, 16, 16, 8, float> acc[2][2];
    #pragma unroll
    for (int i = 0; i < 2; i++)
        #pragma unroll
        for (int j = 0; j < 2; j++)
            wmma::fill_fragment(acc[i][j], 0.0f);

    const int nk = Kit >> 5;

    {
        const float* ap = A + (size_t)(bm + arow) * lda + acol;
        uint32_t ad = as_u + (uint32_t)((arow * 36 + acol) * 4);
        #pragma unroll
        for (int i = 0; i < 4; i++) cp16(ad + i * 16, ap + i * 4);
        const float* bp = W + (size_t)brow * N + bn + bcol;
        uint32_t bd = bs_u + (uint32_t)((brow * 68 + bcol) * 4);
        cp16(bd, bp); cp16(bd + 16, bp + 4);
        cp_commit();
    }

    for (int kt = 0; kt < nk; kt++) {
        int st = kt & 1;
        if (kt + 1 < nk) {
            int k0 = (kt + 1) << 5;
            int s2 = st ^ 1;
            const float* ap = A + (size_t)(bm + arow) * lda + k0 + acol;
            uint32_t ad = as_u + (uint32_t)((s2 * AS_STAGE + arow * 36 + acol) * 4);
            #pragma unroll
            for (int i = 0; i < 4; i++) cp16(ad + i * 16, ap + i * 4);
            const float* bp = W + (size_t)(k0 + brow) * N + bn + bcol;
            uint32_t bd = bs_u + (uint32_t)((s2 * BS_STAGE + brow * 68 + bcol) * 4);
            cp16(bd, bp); cp16(bd + 16, bp + 4);
            cp_commit();
            cp_wait1();
        } else {
            cp_wait0();
        }
        __syncthreads();

        const float* Ab = As + st * AS_STAGE;
        const float* Bb = Bs + st * BS_STAGE;
        #pragma unroll
        for (int kk = 0; kk < 4; kk++) {
            wmma::fragment<wmma::matrix_a, 16, 16, 8, wmma::precision::tf32, wmma::row_major> af[2];
            wmma::fragment<wmma::matrix_b, 16, 16, 8, wmma::precision::tf32, wmma::row_major> bf[2];
            #pragma unroll
            for (int i = 0; i < 2; i++) {
                wmma::load_matrix_sync(af[i], Ab + (wm * 32 + i * 16) * 36 + kk * 8, 36);
                #pragma unroll
                for (int e = 0; e < af[i].num_elements; e++)
                    af[i].x[e] = wmma::__float_to_tf32(af[i].x[e]);
            }
            #pragma unroll
            for (int j = 0; j < 2; j++) {
                wmma::load_matrix_sync(bf[j], Bb + (kk * 8) * 68 + wn * 32 + j * 16, 68);
                #pragma unroll
                for (int e = 0; e < bf[j].num_elements; e++)
                    bf[j].x[e] = wmma::__float_to_tf32(bf[j].x[e]);
            }
            #pragma unroll
            for (int i = 0; i < 2; i++)
                #pragma unroll
                for (int j = 0; j < 2; j++)
                    wmma::mma_sync(acc[i][j], af[i], bf[j], acc[i][j]);
        }
        __syncthreads();
    }

    #pragma unroll
    for (int i = 0; i < 2; i++)
        #pragma unroll
        for (int j = 0; j < 2; j++)
            wmma::store_matrix_sync(C + (size_t)(bm + wm * 32 + i * 16) * N + bn + wn * 32 + j * 16,
                                    acc[i][j], N, wmma::mem_row_major);
}

// fused QKV: blockIdx.x in [0,24); sel = x>>3 chooses weight/output
__global__ __launch_bounds__(256) void gemm_qkv(const float* __restrict__ A,
                                                const float* __restrict__ wq,
                                                const float* __restrict__ wk,
                                                const float* __restrict__ wv,
                                                float* __restrict__ qb,
                                                float* __restrict__ kb,
                                                float* __restrict__ vb) {
    int sel = blockIdx.x >> 3;
    const float* W = (sel == 0) ? wq : (sel == 1) ? wk : wv;
    float* C = (sel == 0) ? qb : (sel == 1) ? kb : vb;
    gemm_body(A, D_MODEL, W, C, HDIM, D_MODEL, blockIdx.y << 7, (blockIdx.x & 7) << 6);
}

// split-K GEMM: blockIdx.z in {0,1} computes K-half -> partial outputs C0/C1
__global__ __launch_bounds__(256) void gemm_splitk(const float* __restrict__ A,
                                                   const float* __restrict__ W,
                                                   float* __restrict__ C0,
                                                   float* __restrict__ C1,
                                                   int N, int K) {
    int kh = K >> 1;
    int koff = blockIdx.z * kh;
    float* C = blockIdx.z ? C1 : C0;
    gemm_body(A + koff, K, W + (size_t)koff * N, C, N, kh,
              blockIdx.y << 7, blockIdx.x << 6);
}

// ---------------- fused W1 GEMM + GEGLU: ua = (hW1v+b1v)*gelu(hW1g+b1g) ------
#define W1_SMEM ((2 * AS_STAGE + 4 * BS_STAGE) * 4)

__global__ __launch_bounds__(256, 2) void gemm_w1glu(const float* __restrict__ A,
                                                     const float* __restrict__ W1,
                                                     const float* __restrict__ b1,
                                                     float* __restrict__ out) {
    extern __shared__ float dyn[];
    float* As = dyn;
    float* Bv = dyn + 2 * AS_STAGE;
    float* Bg = dyn + 2 * AS_STAGE + 2 * BS_STAGE;
    const int tid = threadIdx.x;
    const int warp = tid >> 5, wm = warp & 3, wn = warp >> 2;
    const int bm = blockIdx.y << 7, bn = blockIdx.x << 6;
    const int arow = tid >> 1, acol = (tid & 1) * 16;
    const int brow = tid >> 3, bcol = (tid & 7) * 8;
    uint32_t as_u = (uint32_t)__cvta_generic_to_shared(As);
    uint32_t bv_u = (uint32_t)__cvta_generic_to_shared(Bv);
    uint32_t bg_u = (uint32_t)__cvta_generic_to_shared(Bg);

    wmma::fragment<wmma::accumulator, 16, 16, 8, float> accv[2][2], accg[2][2];
    #pragma unroll
    for (int i = 0; i < 2; i++)
        #pragma unroll
        for (int j = 0; j < 2; j++) {
            wmma::fill_fragment(accv[i][j], 0.0f);
            wmma::fill_fragment(accg[i][j], 0.0f);
        }

    const int NW = 2 * INNER_N;
    {
        const float* ap = A + (size_t)(bm + arow) * D_MODEL + acol;
        uint32_t ad = as_u + (uint32_t)((arow * 36 + acol) * 4);
        #pragma unroll
        for (int i = 0; i < 4; i++) cp16(ad + i * 16, ap + i * 4);
        const float* bpv = W1 + (size_t)brow * NW + bn + bcol;
        uint32_t bdv = bv_u + (uint32_t)((brow * 68 + bcol) * 4);
        cp16(bdv, bpv); cp16(bdv + 16, bpv + 4);
        const float* bpg = bpv + INNER_N;
        uint32_t bdg = bg_u + (uint32_t)((brow * 68 + bcol) * 4);
        cp16(bdg, bpg); cp16(bdg + 16, bpg + 4);
        cp_commit();
    }

    const int nk = D_MODEL >> 5;
    for (int kt = 0; kt < nk; kt++) {
        int st = kt & 1;
        if (kt + 1 < nk) {
            int k0 = (kt + 1) << 5;
            int s2 = st ^ 1;
            const float* ap = A + (size_t)(bm + arow) * D_MODEL + k0 + acol;
            uint32_t ad = as_u + (uint32_t)((s2 * AS_STAGE + arow * 36 + acol) * 4);
            #pragma unroll
            for (int i = 0; i < 4; i++) cp16(ad + i * 16, ap + i * 4);
            const float* bpv = W1 + (size_t)(k0 + brow) * NW + bn + bcol;
            uint32_t bdv = bv_u + (uint32_t)((s2 * BS_STAGE + brow * 68 + bcol) * 4);
            cp16(bdv, bpv); cp16(bdv + 16, bpv + 4);
            const float* bpg = bpv + INNER_N;
            uint32_t bdg = bg_u + (uint32_t)((s2 * BS_STAGE + brow * 68 + bcol) * 4);
            cp16(bdg, bpg); cp16(bdg + 16, bpg + 4);
            cp_commit();
            cp_wait1();
        } else {
            cp_wait0();
        }
        __syncthreads();

        const float* Ab  = As + st * AS_STAGE;
        const float* Bvb = Bv + st * BS_STAGE;
        const float* Bgb = Bg + st * BS_STAGE;
        #pragma unroll
        for (int kk = 0; kk < 4; kk++) {
            wmma::fragment<wmma::matrix_a, 16, 16, 8, wmma::precision::tf32, wmma::row_major> af[2];
            #pragma unroll
            for (int i = 0; i < 2; i++) {
                wmma::load_matrix_sync(af[i], Ab + (wm * 32 + i * 16) * 36 + kk * 8, 36);
                #pragma unroll
                for (int e = 0; e < af[i].num_elements; e++)
                    af[i].x[e] = wmma::__float_to_tf32(af[i].x[e]);
            }
            #pragma unroll
            for (int j = 0; j < 2; j++) {
                wmma::fragment<wmma::matrix_b, 16, 16, 8, wmma::precision::tf32, wmma::row_major> bfv, bfg;
                wmma::load_matrix_sync(bfv, Bvb + (kk * 8) * 68 + wn * 32 + j * 16, 68);
                wmma::load_matrix_sync(bfg, Bgb + (kk * 8) * 68 + wn * 32 + j * 16, 68);
                #pragma unroll
                for (int e = 0; e < bfv.num_elements; e++) {
                    bfv.x[e] = wmma::__float_to_tf32(bfv.x[e]);
                    bfg.x[e] = wmma::__float_to_tf32(bfg.x[e]);
                }
                #pragma unroll
                for (int i = 0; i < 2; i++) {
                    wmma::mma_sync(accv[i][j], af[i], bfv, accv[i][j]);
                    wmma::mma_sync(accg[i][j], af[i], bfg, accg[i][j]);
                }
            }
        }
        __syncthreads();
    }

    float* Sv = dyn;
    float* Sg = dyn + 2 * AS_STAGE;
    #pragma unroll
    for (int i = 0; i < 2; i++)
        #pragma unroll
        for (int j = 0; j < 2; j++) {
            wmma::store_matrix_sync(&Sv[(wm * 32 + i * 16) * 68 + wn * 32 + j * 16],
                                    accv[i][j], 68, wmma::mem_row_major);
            wmma::store_matrix_sync(&Sg[(wm * 32 + i * 16) * 68 + wn * 32 + j * 16],
                                    accg[i][j], 68, wmma::mem_row_major);
        }
    __syncthreads();

    const int er = tid >> 1, ec = (tid & 1) * 32;
    float* orow = out + (size_t)(bm + er) * INNER_N + bn;
    #pragma unroll
    for (int c = 0; c < 32; c++) {
        float vl = Sv[er * 68 + ec + c] + b1[bn + ec + c];
        float gt = Sg[er * 68 + ec + c] + b1[INNER_N + bn + ec + c];
        orow[ec + c] = vl * gt * normcdff(gt);
    }
}

// ---------------- single-pass attention (R11 version — best measured) --------
#define TS 68
#define OFF_K (128 * TS)
#define OFF_V (128 * TS + 64 * TS)
#define OFF_S (128 * TS + 2 * 64 * TS)
#define OFF_P (2 * 128 * TS + 2 * 64 * TS)
#define ATTN_SMEM ((OFF_P + 512) * 4)

__global__ __launch_bounds__(256, 2) void attn_kernel(const float* __restrict__ q,
                                                      const float* __restrict__ k,
                                                      const float* __restrict__ v,
                                                      const int* __restrict__ mask,
                                                      float* __restrict__ o) {
    extern __shared__ float sm[];
    float* Qs = sm;                 // [128][TS]
    float* Ks = sm + OFF_K;         // [64][TS]
    float* Vs = sm + OFF_V;         // [64][TS]
    float* Ss = sm + OFF_S;         // [128][TS]
    float* penal = sm + OFF_P;      // [512]
    uint32_t smem_u = (uint32_t)__cvta_generic_to_shared(sm);

    const int tid = threadIdx.x;
    const int warp = tid >> 5;
    const int wm = warp & 3;
    const int wn = warp >> 2;
    const int qt = blockIdx.x;
    const int b  = blockIdx.y >> 3;
    const int h  = blockIdx.y & 7;
    const float slope = exp2f(-(float)(h + 1));
    const float scale = 0.125f;

    for (int j = tid; j < L_SEQ; j += 256)
        penal[j] = mask[b * L_SEQ + j] ? 0.f : -1e9f;

    {
        int lr = tid >> 1, lc = (tid & 1) * 32;
        const float* qp = q + (size_t)(b * L_SEQ + qt * 128 + lr) * HDIM + h * DHEAD + lc;
        #pragma unroll
        for (int i = 0; i < 8; i++)
            *(float4*)&Qs[lr * TS + lc + i * 4] = *(const float4*)(qp + i * 4);
    }

    const int kr = tid >> 2, kc = (tid & 3) * 16;
    const size_t kvbase = (size_t)(b * L_SEQ + kr) * HDIM + h * DHEAD + kc;
    const uint32_t kd = smem_u + (uint32_t)((OFF_K + kr * TS + kc) * 4);
    const uint32_t vd = smem_u + (uint32_t)((OFF_V + kr * TS + kc) * 4);

    {
        const float* kp = k + kvbase;
        #pragma unroll
        for (int i = 0; i < 4; i++) cp16(kd + i * 16, kp + i * 4);
        cp_commit();
    }
    __syncthreads();

    const int r = tid >> 1, p = tid & 1;
    const int ig = qt * 128 + r;

    float msh = -3e38f;
    for (int jj = 0; jj < 256; jj++) {
        int jg = p * 256 + jj;
        msh = fmaxf(msh, penal[jg] - slope * fabsf((float)(ig - jg)));
    }
    msh = fmaxf(msh, __shfl_xor_sync(0xffffffffu, msh, 1));

    float ssum = 0.f;
    wmma::fragment<wmma::accumulator, 16, 16, 8, float> oacc[2][2];
    #pragma unroll
    for (int i = 0; i < 2; i++)
        #pragma unroll
        for (int j = 0; j < 2; j++)
            wmma::fill_fragment(oacc[i][j], 0.f);

    for (int kt = 0; kt < 8; kt++) {
        {
            const float* vp = v + kvbase + (size_t)kt * 64 * HDIM;
            #pragma unroll
            for (int i = 0; i < 4; i++) cp16(vd + i * 16, vp + i * 4);
            cp_commit();
        }
        cp_wait1();
        __syncthreads();

        #pragma unroll
        for (int i = 0; i < 2; i++) {
            wmma::fragment<wmma::accumulator, 16, 16, 8, float> sacc[2];
            wmma::fill_fragment(sacc[0], 0.f);
            wmma::fill_fragment(sacc[1], 0.f);
            #pragma unroll
            for (int kk = 0; kk < 8; kk++) {
                wmma::fragment<wmma::matrix_a, 16, 16, 8, wmma::precision::tf32, wmma::row_major> af;
                wmma::load_matrix_sync(af, &Qs[(wm * 32 + i * 16) * TS + kk * 8], TS);
                #pragma unroll
                for (int j = 0; j < 2; j++) {
                    wmma::fragment<wmma::matrix_b, 16, 16, 8, wmma::precision::tf32, wmma::col_major> bf;
                    wmma::load_matrix_sync(bf, &Ks[(wn * 32 + j * 16) * TS + kk * 8], TS);
                    wmma::mma_sync(sacc[j], af, bf, sacc[j]);
                }
            }
            #pragma unroll
            for (int j = 0; j < 2; j++)
                wmma::store_matrix_sync(&Ss[(wm * 32 + i * 16) * TS + wn * 32 + j * 16],
                                        sacc[j], TS, wmma::mem_row_major);
        }
        __syncthreads();

        if (kt < 7) {
            const float* kp = k + kvbase + (size_t)(kt + 1) * 64 * HDIM;
            #pragma unroll
            for (int i = 0; i < 4; i++) cp16(kd + i * 16, kp + i * 4);
            cp_commit();
        }

        {
            float* Srow = Ss + r * TS;
            #pragma unroll
            for (int jj = 0; jj < 32; jj++) {
                int jl = p * 32 + jj, jg = kt * 64 + jl;
                float pre = penal[jg] - slope * fabsf((float)(ig - jg)) - msh;
                float e = fexp(fmaf(Srow[jl], scale, pre));
                Srow[jl] = e;
                ssum += e;
            }
        }
        if (kt < 7) cp_wait1(); else cp_wait0();
        __syncthreads();

        #pragma unroll
        for (int i = 0; i < 2; i++)
            #pragma unroll
            for (int kk = 0; kk < 8; kk++) {
                wmma::fragment<wmma::matrix_a, 16, 16, 8, wmma::precision::tf32, wmma::row_major> af;
                wmma::load_matrix_sync(af, &Ss[(wm * 32 + i * 16) * TS + kk * 8], TS);
                #pragma unroll
                for (int j = 0; j < 2; j++) {
                    wmma::fragment<wmma::matrix_b, 16, 16, 8, wmma::precision::tf32, wmma::row_major> bf;
                    wmma::load_matrix_sync(bf, &Vs[(kk * 8) * TS + wn * 32 + j * 16], TS);
                    wmma::mma_sync(oacc[i][j], af, bf, oacc[i][j]);
                }
            }
        __syncthreads();
    }

    ssum += __shfl_xor_sync(0xffffffffu, ssum, 1);
    const float inv = 1.f / ssum;

    #pragma unroll
    for (int i = 0; i < 2; i++)
        #pragma unroll
        for (int j = 0; j < 2; j++)
            wmma::store_matrix_sync(&Ss[(wm * 32 + i * 16) * TS + wn * 32 + j * 16],
                                    oacc[i][j], TS, wmma::mem_row_major);
    __syncthreads();

    {
        int ec = p * 32;
        float* op = o + (size_t)(b * L_SEQ + qt * 128 + r) * HDIM + h * DHEAD + ec;
        #pragma unroll
        for (int i = 0; i < 8; i++) {
            float4 vv = *(float4*)&Ss[r * TS + ec + i * 4];
            vv.x *= inv; vv.y *= inv; vv.z *= inv; vv.w *= inv;
            *(float4*)(op + i * 4) = vv;
        }
    }
}

// ---------------- final projection to 2 logits -------------------------------
__global__ void out_kernel(const float* __restrict__ hh,
                           const float* __restrict__ Wout,
                           const float* __restrict__ bout,
                           float* __restrict__ out) {
    int row = blockIdx.x;
    int d = threadIdx.x;
    float v = hh[(size_t)row * D_MODEL + d];
    float s0 = v * Wout[d * 2 + 0];
    float s1 = v * Wout[d * 2 + 1];
    #pragma unroll
    for (int o2 = 16; o2 > 0; o2 >>= 1) {
        s0 += __shfl_down_sync(0xffffffffu, s0, o2);
        s1 += __shfl_down_sync(0xffffffffu, s1, o2);
    }
    __shared__ float w0[8], w1[8];
    int w = threadIdx.x >> 5, lane = threadIdx.x & 31;
    if (lane == 0) { w0[w] = s0; w1[w] = s1; }
    __syncthreads();
    if (threadIdx.x == 0) {
        float t0 = 0.f, t1 = 0.f;
        #pragma unroll
        for (int i = 0; i < 8; i++) { t0 += w0[i]; t1 += w1[i]; }
        out[row * 2 + 0] = t0 + bout[0];
        out[row * 2 + 1] = t1 + bout[1];
    }
}

// ---------------- host orchestration -----------------------------------------
extern "C" void kernel_launch(void* const* d_in, const int* in_sizes, int n_in,
                              void* d_out, int out_size) {
    (void)in_sizes; (void)n_in; (void)out_size;
    const int*   seq  = (const int*)d_in[0];
    const int*   mask = (const int*)d_in[1];
    const float* emb  = (const float*)d_in[2];
    const float* png  = (const float*)d_in[3];
    const float* pnb  = (const float*)d_in[4];
    const float* ln1g = (const float*)d_in[5];
    const float* ln1b = (const float*)d_in[6];
    const float* Wq   = (const float*)d_in[7];
    const float* Wk   = (const float*)d_in[8];
    const float* Wv   = (const float*)d_in[9];
    const float* Wo   = (const float*)d_in[10];
    const float* ln2g = (const float*)d_in[11];
    const float* ln2b = (const float*)d_in[12];
    const float* W1   = (const float*)d_in[13];
    const float* b1   = (const float*)d_in[14];
    const float* W2   = (const float*)d_in[15];
    const float* b2   = (const float*)d_in[16];
    const float* fng  = (const float*)d_in[17];
    const float* fnb  = (const float*)d_in[18];
    const float* Wout = (const float*)d_in[19];
    const float* bout = (const float*)d_in[20];

    float *x, *h, *t0, *t1, *qb, *kb, *vb, *ab, *uab;
    cudaGetSymbolAddress((void**)&x,   g_x);
    cudaGetSymbolAddress((void**)&h,   g_h);
    cudaGetSymbolAddress((void**)&t0,  g_t0);
    cudaGetSymbolAddress((void**)&t1,  g_t1);
    cudaGetSymbolAddress((void**)&qb,  g_q);
    cudaGetSymbolAddress((void**)&kb,  g_k);
    cudaGetSymbolAddress((void**)&vb,  g_v);
    cudaGetSymbolAddress((void**)&ab,  g_attn);
    cudaGetSymbolAddress((void**)&uab, g_ua);

    cudaFuncSetAttribute(attn_kernel, cudaFuncAttributeMaxDynamicSharedMemorySize, ATTN_SMEM);
    cudaFuncSetAttribute(gemm_qkv,    cudaFuncAttributeMaxDynamicSharedMemorySize, GEMM_SMEM);
    cudaFuncSetAttribute(gemm_splitk, cudaFuncAttributeMaxDynamicSharedMemorySize, GEMM_SMEM);
    cudaFuncSetAttribute(gemm_w1glu,  cudaFuncAttributeMaxDynamicSharedMemorySize, W1_SMEM);

    embed_ln_kernel<<<M_TOK, 256>>>(seq, emb, png, pnb, x);
    ln_kernel<<<M_TOK, 256>>>(x, ln1g, ln1b, h);

    for (int l = 0; l < DEPTH_N; l++) {
        const float* wq  = Wq  + (size_t)l * D_MODEL * HDIM;
        const float* wk  = Wk  + (size_t)l * D_MODEL * HDIM;
        const float* wv  = Wv  + (size_t)l * D_MODEL * HDIM;
        const float* wo  = Wo  + (size_t)l * HDIM * D_MODEL;
        const float* w1  = W1  + (size_t)l * D_MODEL * 2 * INNER_N;
        const float* bb1 = b1  + (size_t)l * 2 * INNER_N;
        const float* w2  = W2  + (size_t)l * INNER_N * D_MODEL;
        const float* bb2 = b2  + (size_t)l * D_MODEL;

        gemm_qkv<<<dim3(24, 32), 256, GEMM_SMEM>>>(h, wq, wk, wv, qb, kb, vb);

        attn_kernel<<<dim3(L_SEQ / 128, 8 * NHEAD), 256, ATTN_SMEM>>>(qb, kb, vb, mask, ab);

        // t0/t1 = K-halves of ab @ wo
        gemm_splitk<<<dim3(D_MODEL / 64, 32, 2), 256, GEMM_SMEM>>>(ab, wo, t0, t1, D_MODEL, HDIM);
        add_ln_kernel<<<M_TOK, 256>>>(x, t0, t1, nullptr,
                                      ln2g + l * D_MODEL, ln2b + l * D_MODEL, h);

        gemm_w1glu<<<dim3(INNER_N / 64, 32), 256, W1_SMEM>>>(h, w1, bb1, uab);

        // t0/t1 = K-halves of ua @ w2
        gemm_splitk<<<dim3(D_MODEL / 64, 32, 2), 256, GEMM_SMEM>>>(uab, w2, t0, t1, D_MODEL, INNER_N);
        if (l < DEPTH_N - 1)
            add_ln_kernel<<<M_TOK, 256>>>(x, t0, t1, bb2,
                                          ln1g + (l + 1) * D_MODEL, ln1b + (l + 1) * D_MODEL, h);
        else
            add_ln_kernel<<<M_TOK, 256>>>(x, t0, t1, bb2, fng, fnb, h);
    }

    out_kernel<<<M_TOK, 256>>>(h, Wout, bout, (float*)d_out);
}